// round 4
// baseline (speedup 1.0000x reference)
#include <cuda_runtime.h>
#include <math.h>

#define BB 8
#define C  64
#define HH 128
#define WW 128
#define HW (HH*WW)
#define CO 128
#define KK 9
#define JCH 28                    // 18 offset + 9 mask + 1 pad
#define CW_SMEM (KK*C*JCH*4)      // 64512 B dynamic smem for combined conv
#define K3_SMEM ((C*128 + C*CO)*4) // 65536 B dynamic smem for k3

// ---------------- scratch (device globals; no allocation) ----------------
__device__ float g_xp [BB*C*HW];   // pre-conv output, NCHW
__device__ float g_xph[BB*HW*C];   // pre-conv output, NHWC (for gathers)
__device__ float g_py [BB*KK*HW];  // absolute sample y coord per (b,kk,pix)
__device__ float g_px [BB*KK*HW];  // absolute sample x coord
__device__ float g_m  [BB*KK*HW];  // modulation mask (2*sigmoid)
__device__ float g_wt [KK*C*CO];   // reg_w transposed to [kk][ci][co]
__device__ float g_cw [KK*C*JCH];  // packed off+mask weights [k][ci][j]
__device__ float g_cb [JCH];       // packed off+mask bias

// ---------------- packed f32x2 helpers -----------------------------------
__device__ __forceinline__ unsigned long long f2_fma(unsigned long long a,
                                                     unsigned long long b,
                                                     unsigned long long c)
{
    unsigned long long d;
    asm("fma.rn.f32x2 %0, %1, %2, %3;" : "=l"(d) : "l"(a), "l"(b), "l"(c));
    return d;
}
__device__ __forceinline__ unsigned long long f2_dup(float x)
{
    unsigned long long d;
    asm("mov.b64 %0, {%1, %1};" : "=l"(d) : "f"(x));
    return d;
}
__device__ __forceinline__ unsigned long long f2_pack(float lo, float hi)
{
    unsigned long long d;
    asm("mov.b64 %0, {%1, %2};" : "=l"(d) : "f"(lo), "f"(hi));
    return d;
}
__device__ __forceinline__ void f2_unpack(unsigned long long v, float& lo, float& hi)
{
    asm("mov.b64 {%0, %1}, %2;" : "=f"(lo), "=f"(hi) : "l"(v));
}

// ---------------- K0a: transpose reg_w -> [kk][ci][co] -------------------
__global__ void k0_wt(const float* __restrict__ rw)
{
    int i = blockIdx.x * 256 + threadIdx.x;
    if (i >= KK*C*CO) return;
    int co = i % CO;
    int ci = (i / CO) % C;
    int kk = i / (CO*C);
    g_wt[i] = rw[(co*C + ci)*KK + kk];
}

// ---------------- K0b: pack off+mask weights -> [k][ci][j(28)] -----------
__global__ void k0_cw(const float* __restrict__ ow, const float* __restrict__ ob,
                      const float* __restrict__ mw, const float* __restrict__ mb)
{
    int i = blockIdx.x * 256 + threadIdx.x;
    if (i < KK*C*JCH) {
        int j  = i % JCH;
        int ci = (i / JCH) % C;
        int k  = i / (JCH*C);
        float v = 0.0f;
        if (j < 18)      v = ow[(j*C + ci)*KK + k];
        else if (j < 27) v = mw[((j-18)*C + ci)*KK + k];
        g_cw[i] = v;
    }
    if (i < JCH) {
        float v = 0.0f;
        if (i < 18)      v = ob[i];
        else if (i < 27) v = mb[i-18];
        g_cb[i] = v;
    }
}

// ---------------- K1: 1x1 conv (packed FFMA2), write NCHW + NHWC ---------
__global__ __launch_bounds__(256) void k1_pre(const float* __restrict__ x,
                                              const float* __restrict__ pw,
                                              const float* __restrict__ pb)
{
    __shared__ float ws[C*C];          // transposed: [ci][co]
    int b = blockIdx.y;
    int p = blockIdx.x * 256 + threadIdx.x;
    for (int i = threadIdx.x; i < C*C; i += 256) {
        int ci = i >> 6, co = i & 63;
        ws[i] = pw[co*C + ci];
    }
    __syncthreads();

    float xv[C];
    const float* xb = x + (size_t)b*C*HW + p;
#pragma unroll
    for (int ci = 0; ci < C; ci++) xv[ci] = xb[(size_t)ci*HW];

    float* outh = g_xph + ((size_t)b*HW + p)*C;
    float* outc = g_xp  + (size_t)b*C*HW + p;

#pragma unroll 1
    for (int chunk = 0; chunk < 4; chunk++) {
        int co16 = chunk * 16;
        unsigned long long acc[8];
#pragma unroll
        for (int j = 0; j < 8; j++)
            acc[j] = f2_pack(pb[co16 + 2*j], pb[co16 + 2*j + 1]);
#pragma unroll 4
        for (int ci = 0; ci < C; ci++) {
            unsigned long long sd = f2_dup(xv[ci]);
            const float* wr = ws + ci*C + co16;
            ulonglong2 w0 = *(const ulonglong2*)(wr + 0);
            ulonglong2 w1 = *(const ulonglong2*)(wr + 4);
            ulonglong2 w2 = *(const ulonglong2*)(wr + 8);
            ulonglong2 w3 = *(const ulonglong2*)(wr + 12);
            acc[0] = f2_fma(w0.x, sd, acc[0]);
            acc[1] = f2_fma(w0.y, sd, acc[1]);
            acc[2] = f2_fma(w1.x, sd, acc[2]);
            acc[3] = f2_fma(w1.y, sd, acc[3]);
            acc[4] = f2_fma(w2.x, sd, acc[4]);
            acc[5] = f2_fma(w2.y, sd, acc[5]);
            acc[6] = f2_fma(w3.x, sd, acc[6]);
            acc[7] = f2_fma(w3.y, sd, acc[7]);
        }
        float o[16];
#pragma unroll
        for (int j = 0; j < 8; j++) f2_unpack(acc[j], o[2*j], o[2*j+1]);
#pragma unroll
        for (int q = 0; q < 4; q++) {
            float4 r; r.x = o[4*q]; r.y = o[4*q+1]; r.z = o[4*q+2]; r.w = o[4*q+3];
            *(float4*)(outh + co16 + 4*q) = r;
        }
#pragma unroll
        for (int j = 0; j < 16; j++)
            outc[(size_t)(co16 + j)*HW] = o[j];
    }
}

// ---------------- K2: combined offset+mask conv, 2 px / thread -----------
// block 256 threads = 4 rows; thread handles pixels (ho, 2wi), (ho, 2wi+1).
__global__ __launch_bounds__(256, 1) void k2_comb()
{
    extern __shared__ float ws[];      // [k][ci][28]  (64512 B dynamic)
    int b  = blockIdx.y;
    int wi = threadIdx.x & 63;
    int ho = blockIdx.x*4 + (threadIdx.x >> 6);
    int c0 = 2*wi;                     // pixel 0 column
    // pixel 1 column = c0+1

    for (int i = threadIdx.x; i < KK*C*JCH/4; i += 256)
        ((float4*)ws)[i] = ((const float4*)g_cw)[i];
    __syncthreads();

    unsigned long long a0[14], a1[14];
#pragma unroll
    for (int jp = 0; jp < 14; jp++) {
        unsigned long long bv = f2_pack(g_cb[2*jp], g_cb[2*jp+1]);
        a0[jp] = bv; a1[jp] = bv;
    }

    const float* xb = g_xp + (size_t)b*C*HW;
#pragma unroll
    for (int ky = 0; ky < 3; ky++) {
        int y = ho - 1 + ky; if (y < 0 || y >= HH) continue;
#pragma unroll
        for (int kx = 0; kx < 3; kx++) {
            int lc0 = c0 - 1 + kx;          // px0 source col
            int lc1 = lc0 + 1;              // px1 source col
            float m0 = (lc0 >= 0 && lc0 < WW) ? 1.0f : 0.0f;
            float m1 = (lc1 < WW) ? 1.0f : 0.0f;   // lc1 >= 0 always
            int a0c = min(max(lc0, 0), WW-1);
            int a1c = min(lc1, WW-1);
            const float* s0 = xb + y*WW + a0c;
            const float* s1 = xb + y*WW + a1c;
            const float* wk = ws + (ky*3 + kx)*C*JCH;
#pragma unroll 2
            for (int ci = 0; ci < C; ci++) {
                unsigned long long sd0 = f2_dup(s0[(size_t)ci*HW] * m0);
                unsigned long long sd1 = f2_dup(s1[(size_t)ci*HW] * m1);
                const float* wr = wk + ci*JCH;
                ulonglong2 w0 = *(const ulonglong2*)(wr + 0);
                ulonglong2 w1 = *(const ulonglong2*)(wr + 4);
                ulonglong2 w2 = *(const ulonglong2*)(wr + 8);
                ulonglong2 w3 = *(const ulonglong2*)(wr + 12);
                ulonglong2 w4 = *(const ulonglong2*)(wr + 16);
                ulonglong2 w5 = *(const ulonglong2*)(wr + 20);
                ulonglong2 w6 = *(const ulonglong2*)(wr + 24);
                a0[0]  = f2_fma(w0.x, sd0, a0[0]);   a1[0]  = f2_fma(w0.x, sd1, a1[0]);
                a0[1]  = f2_fma(w0.y, sd0, a0[1]);   a1[1]  = f2_fma(w0.y, sd1, a1[1]);
                a0[2]  = f2_fma(w1.x, sd0, a0[2]);   a1[2]  = f2_fma(w1.x, sd1, a1[2]);
                a0[3]  = f2_fma(w1.y, sd0, a0[3]);   a1[3]  = f2_fma(w1.y, sd1, a1[3]);
                a0[4]  = f2_fma(w2.x, sd0, a0[4]);   a1[4]  = f2_fma(w2.x, sd1, a1[4]);
                a0[5]  = f2_fma(w2.y, sd0, a0[5]);   a1[5]  = f2_fma(w2.y, sd1, a1[5]);
                a0[6]  = f2_fma(w3.x, sd0, a0[6]);   a1[6]  = f2_fma(w3.x, sd1, a1[6]);
                a0[7]  = f2_fma(w3.y, sd0, a0[7]);   a1[7]  = f2_fma(w3.y, sd1, a1[7]);
                a0[8]  = f2_fma(w4.x, sd0, a0[8]);   a1[8]  = f2_fma(w4.x, sd1, a1[8]);
                a0[9]  = f2_fma(w4.y, sd0, a0[9]);   a1[9]  = f2_fma(w4.y, sd1, a1[9]);
                a0[10] = f2_fma(w5.x, sd0, a0[10]);  a1[10] = f2_fma(w5.x, sd1, a1[10]);
                a0[11] = f2_fma(w5.y, sd0, a0[11]);  a1[11] = f2_fma(w5.y, sd1, a1[11]);
                a0[12] = f2_fma(w6.x, sd0, a0[12]);  a1[12] = f2_fma(w6.x, sd1, a1[12]);
                a0[13] = f2_fma(w6.y, sd0, a0[13]);  a1[13] = f2_fma(w6.y, sd1, a1[13]);
            }
        }
    }

    float o0[28], o1[28];
#pragma unroll
    for (int jp = 0; jp < 14; jp++) {
        f2_unpack(a0[jp], o0[2*jp], o0[2*jp+1]);
        f2_unpack(a1[jp], o1[2*jp], o1[2*jp+1]);
    }

    int p = ho*WW + c0;
#pragma unroll
    for (int kk = 0; kk < KK; kk++) {
        size_t o = ((size_t)b*KK + kk)*HW + p;
        float byv = (float)(ho - 1 + kk/3);
        float bxv = (float)(c0 - 1 + kk%3);
        g_py[o]   = byv + o0[2*kk];
        g_py[o+1] = byv + o1[2*kk];
        g_px[o]   = bxv       + o0[2*kk+1];
        g_px[o+1] = bxv + 1.f + o1[2*kk+1];
        g_m [o]   = 2.0f / (1.0f + expf(-o0[18+kk]));
        g_m [o+1] = 2.0f / (1.0f + expf(-o1[18+kk]));
    }
}

// ---------------- K3: bilinear sample + modulate + GEMM (FFMA2) ----------
// block: 128 pixels x 128 couts, 256 threads, 8co x 8px register tile.
__global__ __launch_bounds__(256, 1) void k3_main(float* __restrict__ out)
{
    extern __shared__ float sm3[];
    float* sS = sm3;               // [ci][128 px]  32768 B
    float* sW = sm3 + C*128;       // [ci][128 co]  32768 B

    int b   = blockIdx.y;
    int p0  = blockIdx.x * 128;
    int tid = threadIdx.x;
    int pxg = tid & 15;            // pixel group (8 pixels each)
    int cog = tid >> 4;            // cout group  (8 couts each)
    int pxl = tid >> 1;            // sampling: pixel 0..127
    int part = tid & 1;            // sampling: channel half (32 ch)

    unsigned long long acc2[4][8];
#pragma unroll
    for (int k = 0; k < 4; k++)
#pragma unroll
        for (int i = 0; i < 8; i++) acc2[k][i] = 0ull;

    const float* xb = g_xph + (size_t)b*HW*C;

    for (int kk = 0; kk < KK; kk++) {
        __syncthreads();   // protect previous iteration's smem reads

        // --- load weight tile [ci][co]
        {
            const float* wsrc = g_wt + kk*C*CO;
#pragma unroll
            for (int r = 0; r < 8; r++) {
                int idx = (tid + r*256) * 4;
                *(float4*)&sW[idx] = *(const float4*)&wsrc[idx];
            }
        }

        // --- bilinear sample 128 px x 64 ch into sS (2 threads/px, 32 ch each)
        {
            int p = p0 + pxl;
            size_t o = ((size_t)b*KK + kk)*HW + p;
            float py = g_py[o], px = g_px[o], m = g_m[o];
            float y0f = floorf(py), x0f = floorf(px);
            float wy = py - y0f,   wx = px - x0f;
            int y0 = (int)y0f, x0 = (int)x0f;
            int y1 = y0 + 1,   x1 = x0 + 1;
            float vy0 = (y0 >= 0 && y0 < HH) ? 1.0f : 0.0f;
            float vy1 = (y1 >= 0 && y1 < HH) ? 1.0f : 0.0f;
            float vx0 = (x0 >= 0 && x0 < WW) ? 1.0f : 0.0f;
            float vx1 = (x1 >= 0 && x1 < WW) ? 1.0f : 0.0f;
            float w00 = (1.0f-wy)*(1.0f-wx)*vy0*vx0*m;
            float w01 = (1.0f-wy)*wx       *vy0*vx1*m;
            float w10 = wy*(1.0f-wx)       *vy1*vx0*m;
            float w11 = wy*wx              *vy1*vx1*m;
            int y0c = min(max(y0,0),HH-1), y1c = min(max(y1,0),HH-1);
            int x0c = min(max(x0,0),WW-1), x1c = min(max(x1,0),WW-1);
            const float* p00 = xb + ((size_t)y0c*WW + x0c)*C + part*32;
            const float* p01 = xb + ((size_t)y0c*WW + x1c)*C + part*32;
            const float* p10 = xb + ((size_t)y1c*WW + x0c)*C + part*32;
            const float* p11 = xb + ((size_t)y1c*WW + x1c)*C + part*32;
#pragma unroll
            for (int i = 0; i < 8; i++) {
                float4 a  = *(const float4*)(p00 + 4*i);
                float4 b4 = *(const float4*)(p01 + 4*i);
                float4 c  = *(const float4*)(p10 + 4*i);
                float4 d  = *(const float4*)(p11 + 4*i);
                int cib = part*32 + 4*i;
                sS[(cib+0)*128 + pxl] = w00*a.x + w01*b4.x + w10*c.x + w11*d.x;
                sS[(cib+1)*128 + pxl] = w00*a.y + w01*b4.y + w10*c.y + w11*d.y;
                sS[(cib+2)*128 + pxl] = w00*a.z + w01*b4.z + w10*c.z + w11*d.z;
                sS[(cib+3)*128 + pxl] = w00*a.w + w01*b4.w + w10*c.w + w11*d.w;
            }
        }
        __syncthreads();

        // --- GEMM: acc2[4 copair][8 px] += W2[ci][copair] * dup(S[ci][px])
#pragma unroll 2
        for (int ci = 0; ci < C; ci++) {
            float4 sa = *(const float4*)&sS[ci*128 + pxg*8];
            float4 sb = *(const float4*)&sS[ci*128 + pxg*8 + 4];
            unsigned long long sd[8];
            sd[0] = f2_dup(sa.x); sd[1] = f2_dup(sa.y);
            sd[2] = f2_dup(sa.z); sd[3] = f2_dup(sa.w);
            sd[4] = f2_dup(sb.x); sd[5] = f2_dup(sb.y);
            sd[6] = f2_dup(sb.z); sd[7] = f2_dup(sb.w);
            ulonglong2 wa = *(const ulonglong2*)&sW[ci*CO + cog*8];
            ulonglong2 wb = *(const ulonglong2*)&sW[ci*CO + cog*8 + 4];
#pragma unroll
            for (int i = 0; i < 8; i++) {
                acc2[0][i] = f2_fma(wa.x, sd[i], acc2[0][i]);
                acc2[1][i] = f2_fma(wa.y, sd[i], acc2[1][i]);
                acc2[2][i] = f2_fma(wb.x, sd[i], acc2[2][i]);
                acc2[3][i] = f2_fma(wb.y, sd[i], acc2[3][i]);
            }
        }
    }

    // --- epilogue: unpack co-pairs, write out[b][co][p]
#pragma unroll
    for (int k = 0; k < 4; k++) {
        float lo[8], hi[8];
#pragma unroll
        for (int i = 0; i < 8; i++) f2_unpack(acc2[k][i], lo[i], hi[i]);
        int co = cog*8 + 2*k;
        float* orow0 = &out[((size_t)b*CO + co    )*HW + p0 + pxg*8];
        float* orow1 = &out[((size_t)b*CO + co + 1)*HW + p0 + pxg*8];
        float4 r0a; r0a.x = lo[0]; r0a.y = lo[1]; r0a.z = lo[2]; r0a.w = lo[3];
        float4 r0b; r0b.x = lo[4]; r0b.y = lo[5]; r0b.z = lo[6]; r0b.w = lo[7];
        float4 r1a; r1a.x = hi[0]; r1a.y = hi[1]; r1a.z = hi[2]; r1a.w = hi[3];
        float4 r1b; r1b.x = hi[4]; r1b.y = hi[5]; r1b.z = hi[6]; r1b.w = hi[7];
        *(float4*)(orow0)     = r0a;
        *(float4*)(orow0 + 4) = r0b;
        *(float4*)(orow1)     = r1a;
        *(float4*)(orow1 + 4) = r1b;
    }
}

// ---------------- launch --------------------------------------------------
extern "C" void kernel_launch(void* const* d_in, const int* in_sizes, int n_in,
                              void* d_out, int out_size)
{
    const float* x     = (const float*)d_in[0];
    const float* pre_w = (const float*)d_in[1];
    const float* pre_b = (const float*)d_in[2];
    const float* off_w = (const float*)d_in[3];
    const float* off_b = (const float*)d_in[4];
    const float* mod_w = (const float*)d_in[5];
    const float* mod_b = (const float*)d_in[6];
    const float* reg_w = (const float*)d_in[7];
    float* out = (float*)d_out;

    cudaFuncSetAttribute(k2_comb, cudaFuncAttributeMaxDynamicSharedMemorySize, CW_SMEM);
    cudaFuncSetAttribute(k3_main, cudaFuncAttributeMaxDynamicSharedMemorySize, K3_SMEM);

    k1_pre <<<dim3(HW/256, BB), 256>>>(x, pre_w, pre_b);
    k0_wt  <<<(KK*C*CO + 255)/256, 256>>>(reg_w);
    k0_cw  <<<(KK*C*JCH + 255)/256, 256>>>(off_w, off_b, mod_w, mod_b);
    k2_comb<<<dim3(HH/4, BB), 256, CW_SMEM>>>();
    k3_main<<<dim3(HW/128, BB), 256, K3_SMEM>>>(out);
}